// round 2
// baseline (speedup 1.0000x reference)
#include <cuda_runtime.h>
#include <cuda_bf16.h>
#include <math.h>

// Problem constants
#define BATCH  8
#define T_DIM  1024
#define I_DIM  576
#define C_DIM  1024
#define N_HEAD 16
#define HD     64

// ---------------------------------------------------------------------------
// Scratch (device globals; no allocation allowed)
// ---------------------------------------------------------------------------
__device__ float g_q [BATCH * T_DIM * C_DIM];        // 33.5 MB
__device__ float g_kv[BATCH * I_DIM * 2 * C_DIM];    // 37.7 MB
__device__ float g_y [BATCH * T_DIM * C_DIM];        // 33.5 MB

// ---------------------------------------------------------------------------
// TF32 helpers (3xTF32 split: x = hi + lo, both tf32-representable)
// ---------------------------------------------------------------------------
__device__ __forceinline__ float tf32_rna(float x) {
    unsigned u;
    asm("cvt.rna.tf32.f32 %0, %1;" : "=r"(u) : "f"(x));
    return __uint_as_float(u);
}

__device__ __forceinline__ void mma_tf32(float* c, const unsigned* a, const unsigned* b) {
    asm volatile(
        "mma.sync.aligned.m16n8k8.row.col.f32.tf32.tf32.f32 "
        "{%0,%1,%2,%3}, {%4,%5,%6,%7}, {%8,%9}, {%0,%1,%2,%3};\n"
        : "+f"(c[0]), "+f"(c[1]), "+f"(c[2]), "+f"(c[3])
        : "r"(a[0]), "r"(a[1]), "r"(a[2]), "r"(a[3]), "r"(b[0]), "r"(b[1]));
}

// ---------------------------------------------------------------------------
// GEMM NT via tensor cores (3xTF32): C[M,N] = A[M,K] * B[N,K]^T + bias[N]
// Block tile 128x128x32, 256 threads = 8 warps (2m x 4n), warp tile 64x32.
// hi/lo stored interleaved in smem as float2 -> one LDS.64 per fragment reg.
// ---------------------------------------------------------------------------
#define BM 128
#define BN 128
#define BK 32
#define SAS (BM + 4)            // float2 stride per k-row
#define GEMM_SMEM_BYTES (2 * BK * SAS * (int)sizeof(float2))   // 67584 B

__global__ __launch_bounds__(256) void sgemm_tf32(
    const float* __restrict__ A, const float* __restrict__ B,
    const float* __restrict__ bias, float* __restrict__ C,
    int M, int N, int K)
{
    extern __shared__ float2 sm2[];
    float2* sA = sm2;                 // [BK][SAS]  (.x = hi, .y = lo)
    float2* sB = sA + BK * SAS;       // [BK][SAS]

    const int tid  = threadIdx.x;
    const int m0   = blockIdx.y * BM;
    const int n0   = blockIdx.x * BN;
    const int wid  = tid >> 5;
    const int lane = tid & 31;
    const int g    = lane >> 2;       // 0..7
    const int tig  = lane & 3;        // 0..3
    const int wm   = (wid >> 2) * 64; // warp m offset
    const int wn   = (wid & 3) * 32;  // warp n offset

    // global loaders: 32 rows x 8 float4-cols per pass, 4 passes
    const int lm = tid >> 3;          // 0..31
    const int lk = (tid & 7) << 2;    // 0,4,...,28

    float acc[4][4][4] = {};

    const float* Ag = A + (size_t)(m0 + lm) * K + lk;
    const float* Bg = B + (size_t)(n0 + lm) * K + lk;

    for (int k0 = 0; k0 < K; k0 += BK) {
        float4 av[4], bv[4];
#pragma unroll
        for (int p = 0; p < 4; p++) {
            av[p] = *(const float4*)(Ag + (size_t)(p * 32) * K + k0);
            bv[p] = *(const float4*)(Bg + (size_t)(p * 32) * K + k0);
        }

        __syncthreads();   // previous iteration's fragment loads done

#pragma unroll
        for (int p = 0; p < 4; p++) {
            const int m = lm + p * 32;
            float va[4] = {av[p].x, av[p].y, av[p].z, av[p].w};
            float vb[4] = {bv[p].x, bv[p].y, bv[p].z, bv[p].w};
#pragma unroll
            for (int j = 0; j < 4; j++) {
                float hi = tf32_rna(va[j]);
                float lo = tf32_rna(va[j] - hi);
                sA[(lk + j) * SAS + m] = make_float2(hi, lo);
                hi = tf32_rna(vb[j]);
                lo = tf32_rna(vb[j] - hi);
                sB[(lk + j) * SAS + m] = make_float2(hi, lo);
            }
        }

        __syncthreads();

#pragma unroll
        for (int kk = 0; kk < BK; kk += 8) {
            unsigned ah[4][4], al[4][4], bh[4][2], bl[4][2];
#pragma unroll
            for (int i = 0; i < 4; i++) {
                const int col = wm + 16 * i + g;
                float2 f0 = sA[(kk + tig)     * SAS + col];
                float2 f1 = sA[(kk + tig)     * SAS + col + 8];
                float2 f2 = sA[(kk + tig + 4) * SAS + col];
                float2 f3 = sA[(kk + tig + 4) * SAS + col + 8];
                ah[i][0] = __float_as_uint(f0.x); al[i][0] = __float_as_uint(f0.y);
                ah[i][1] = __float_as_uint(f1.x); al[i][1] = __float_as_uint(f1.y);
                ah[i][2] = __float_as_uint(f2.x); al[i][2] = __float_as_uint(f2.y);
                ah[i][3] = __float_as_uint(f3.x); al[i][3] = __float_as_uint(f3.y);
            }
#pragma unroll
            for (int j = 0; j < 4; j++) {
                const int col = wn + 8 * j + g;
                float2 f0 = sB[(kk + tig)     * SAS + col];
                float2 f1 = sB[(kk + tig + 4) * SAS + col];
                bh[j][0] = __float_as_uint(f0.x); bl[j][0] = __float_as_uint(f0.y);
                bh[j][1] = __float_as_uint(f1.x); bl[j][1] = __float_as_uint(f1.y);
            }
#pragma unroll
            for (int i = 0; i < 4; i++)
#pragma unroll
                for (int j = 0; j < 4; j++) {
                    mma_tf32(acc[i][j], ah[i], bh[j]);
                    mma_tf32(acc[i][j], al[i], bh[j]);
                    mma_tf32(acc[i][j], ah[i], bl[j]);
                }
        }
    }

    // epilogue: c0,c1 -> (row, col 2tig..+1); c2,c3 -> (row+8, same cols)
#pragma unroll
    for (int i = 0; i < 4; i++) {
        const int r0 = m0 + wm + 16 * i + g;
#pragma unroll
        for (int j = 0; j < 4; j++) {
            const int cb = n0 + wn + 8 * j + 2 * tig;
            const float b0 = bias[cb], b1 = bias[cb + 1];
            float2* p0 = (float2*)(C + (size_t)r0 * N + cb);
            float2* p1 = (float2*)(C + (size_t)(r0 + 8) * N + cb);
            *p0 = make_float2(acc[i][j][0] + b0, acc[i][j][1] + b1);
            *p1 = make_float2(acc[i][j][2] + b0, acc[i][j][3] + b1);
        }
    }
}

// ---------------------------------------------------------------------------
// Attention: per (b, h, 32-row t-tile). Full S row in smem, two-pass softmax.
// (unchanged from R1 baseline — known correct; R3 target)
// ---------------------------------------------------------------------------
#define SQ_STRIDE 65
#define SS_STRIDE 577
#define ST_STRIDE 65
#define ATTN_SMEM_FLOATS (32 * SQ_STRIDE + 32 * SS_STRIDE + 64 * ST_STRIDE + 32)
#define ATTN_SMEM_BYTES  (ATTN_SMEM_FLOATS * 4)

__global__ __launch_bounds__(256) void attn_kernel(
    const float* __restrict__ qb, const float* __restrict__ kvb,
    float* __restrict__ yb)
{
    extern __shared__ float sm[];
    float* sQ = sm;                              // [32][65]
    float* sS = sQ + 32 * SQ_STRIDE;             // [32][577]
    float* sT = sS + 32 * SS_STRIDE;             // [64][65]   K/V staging
    float* sL = sT + 64 * ST_STRIDE;             // [32]       row sums

    const int tid = threadIdx.x;
    const int b = blockIdx.z;
    const int h = blockIdx.y;
    const int t0 = blockIdx.x * 32;

    {
        const float* qptr = qb + ((size_t)b * T_DIM + t0) * C_DIM + h * HD;
        for (int idx = tid; idx < 32 * 64; idx += 256) {
            int t = idx >> 6, d = idx & 63;
            sQ[t * SQ_STRIDE + d] = qptr[(size_t)t * C_DIM + d];
        }
    }
    __syncthreads();

    const int tt   = tid >> 4;
    const int ii   = tid & 15;
    const int trow = tt * 2;
    const int icol = ii * 4;

    // ----- Phase 1: S = (Q K^T) * 1/sqrt(64) -----
    for (int i0 = 0; i0 < I_DIM; i0 += 64) {
        const float* kptr = kvb + ((size_t)b * I_DIM + i0) * (2 * C_DIM) + h * HD;
        for (int idx = tid; idx < 64 * 64; idx += 256) {
            int i = idx >> 6, d = idx & 63;
            sT[i * ST_STRIDE + d] = kptr[(size_t)i * (2 * C_DIM) + d];
        }
        __syncthreads();

        float a00 = 0.f, a01 = 0.f, a02 = 0.f, a03 = 0.f;
        float a10 = 0.f, a11 = 0.f, a12 = 0.f, a13 = 0.f;
        const float* q0p = &sQ[trow * SQ_STRIDE];
        const float* q1p = &sQ[(trow + 1) * SQ_STRIDE];
        const float* k0p = &sT[(icol + 0) * ST_STRIDE];
        const float* k1p = &sT[(icol + 1) * ST_STRIDE];
        const float* k2p = &sT[(icol + 2) * ST_STRIDE];
        const float* k3p = &sT[(icol + 3) * ST_STRIDE];
#pragma unroll 16
        for (int d = 0; d < 64; d++) {
            float q0 = q0p[d], q1 = q1p[d];
            float k0 = k0p[d], k1 = k1p[d], k2 = k2p[d], k3 = k3p[d];
            a00 += q0 * k0; a01 += q0 * k1; a02 += q0 * k2; a03 += q0 * k3;
            a10 += q1 * k0; a11 += q1 * k1; a12 += q1 * k2; a13 += q1 * k3;
        }
        float* s0 = &sS[trow * SS_STRIDE + i0 + icol];
        float* s1 = &sS[(trow + 1) * SS_STRIDE + i0 + icol];
        s0[0] = a00 * 0.125f; s0[1] = a01 * 0.125f; s0[2] = a02 * 0.125f; s0[3] = a03 * 0.125f;
        s1[0] = a10 * 0.125f; s1[1] = a11 * 0.125f; s1[2] = a12 * 0.125f; s1[3] = a13 * 0.125f;
        __syncthreads();
    }

    // ----- Phase 2: softmax -----
    {
        const int row = tid >> 3, g = tid & 7;
        float* sr = &sS[row * SS_STRIDE];
        float m = -1e30f;
        for (int i = g; i < I_DIM; i += 8) m = fmaxf(m, sr[i]);
        m = fmaxf(m, __shfl_xor_sync(0xffffffffu, m, 1));
        m = fmaxf(m, __shfl_xor_sync(0xffffffffu, m, 2));
        m = fmaxf(m, __shfl_xor_sync(0xffffffffu, m, 4));
        float s = 0.f;
        for (int i = g; i < I_DIM; i += 8) {
            float e = __expf(sr[i] - m);
            sr[i] = e;
            s += e;
        }
        s += __shfl_xor_sync(0xffffffffu, s, 1);
        s += __shfl_xor_sync(0xffffffffu, s, 2);
        s += __shfl_xor_sync(0xffffffffu, s, 4);
        if (g == 0) sL[row] = s;
    }
    __syncthreads();

    // ----- Phase 3: Y = P V -----
    float y00 = 0.f, y01 = 0.f, y02 = 0.f, y03 = 0.f;
    float y10 = 0.f, y11 = 0.f, y12 = 0.f, y13 = 0.f;
    for (int i0 = 0; i0 < I_DIM; i0 += 64) {
        const float* vptr = kvb + ((size_t)b * I_DIM + i0) * (2 * C_DIM) + C_DIM + h * HD;
        for (int idx = tid; idx < 64 * 64; idx += 256) {
            int i = idx >> 6, d = idx & 63;
            sT[i * ST_STRIDE + d] = vptr[(size_t)i * (2 * C_DIM) + d];
        }
        __syncthreads();

        const float* p0p = &sS[trow * SS_STRIDE + i0];
        const float* p1p = &sS[(trow + 1) * SS_STRIDE + i0];
#pragma unroll 8
        for (int i = 0; i < 64; i++) {
            float p0 = p0p[i], p1 = p1p[i];
            const float* vp = &sT[i * ST_STRIDE + icol];
            float v0 = vp[0], v1 = vp[1], v2 = vp[2], v3 = vp[3];
            y00 += p0 * v0; y01 += p0 * v1; y02 += p0 * v2; y03 += p0 * v3;
            y10 += p1 * v0; y11 += p1 * v1; y12 += p1 * v2; y13 += p1 * v3;
        }
        __syncthreads();
    }

    const float inv0 = 1.0f / sL[trow];
    const float inv1 = 1.0f / sL[trow + 1];
    float* y0p = yb + ((size_t)b * T_DIM + t0 + trow) * C_DIM + h * HD + icol;
    float* y1p = y0p + C_DIM;
    y0p[0] = y00 * inv0; y0p[1] = y01 * inv0; y0p[2] = y02 * inv0; y0p[3] = y03 * inv0;
    y1p[0] = y10 * inv1; y1p[1] = y11 * inv1; y1p[2] = y12 * inv1; y1p[3] = y13 * inv1;
}

// ---------------------------------------------------------------------------
// Launch
// ---------------------------------------------------------------------------
extern "C" void kernel_launch(void* const* d_in, const int* in_sizes, int n_in,
                              void* d_out, int out_size)
{
    const float* x   = (const float*)d_in[0];
    const float* enc = (const float*)d_in[1];
    const float* Wq  = (const float*)d_in[2];
    const float* bq  = (const float*)d_in[3];
    const float* Wkv = (const float*)d_in[4];
    const float* bkv = (const float*)d_in[5];
    const float* Wo  = (const float*)d_in[6];
    const float* bo  = (const float*)d_in[7];
    float* out = (float*)d_out;

    float *qp, *kvp, *yp;
    cudaGetSymbolAddress((void**)&qp,  g_q);
    cudaGetSymbolAddress((void**)&kvp, g_kv);
    cudaGetSymbolAddress((void**)&yp,  g_y);

    cudaFuncSetAttribute(sgemm_tf32,
                         cudaFuncAttributeMaxDynamicSharedMemorySize,
                         GEMM_SMEM_BYTES);
    cudaFuncSetAttribute(attn_kernel,
                         cudaFuncAttributeMaxDynamicSharedMemorySize,
                         ATTN_SMEM_BYTES);

    // Q = x @ Wq^T + bq           : M=8192, N=1024, K=1024
    sgemm_tf32<<<dim3(C_DIM / BN, (BATCH * T_DIM) / BM), 256, GEMM_SMEM_BYTES>>>(
        x, Wq, bq, qp, BATCH * T_DIM, C_DIM, C_DIM);

    // KV = enc @ Wkv^T + bkv      : M=4608, N=2048, K=1024
    sgemm_tf32<<<dim3((2 * C_DIM) / BN, (BATCH * I_DIM) / BM), 256, GEMM_SMEM_BYTES>>>(
        enc, Wkv, bkv, kvp, BATCH * I_DIM, 2 * C_DIM, C_DIM);

    // attention -> y
    attn_kernel<<<dim3(T_DIM / 32, N_HEAD, BATCH), 256, ATTN_SMEM_BYTES>>>(
        qp, kvp, yp);

    // out = y @ Wo^T + bo         : M=8192, N=1024, K=1024
    sgemm_tf32<<<dim3(C_DIM / BN, (BATCH * T_DIM) / BM), 256, GEMM_SMEM_BYTES>>>(
        yp, Wo, bo, out, BATCH * T_DIM, C_DIM, C_DIM);
}

// round 4
// speedup vs baseline: 1.5392x; 1.5392x over previous
#include <cuda_runtime.h>
#include <cuda_bf16.h>
#include <math.h>

// Problem constants
#define BATCH  8
#define T_DIM  1024
#define I_DIM  576
#define C_DIM  1024
#define N_HEAD 16
#define HD     64

// ---------------------------------------------------------------------------
// Scratch (device globals; no allocation allowed)
// ---------------------------------------------------------------------------
__device__ float g_q [BATCH * T_DIM * C_DIM];
__device__ float g_kv[BATCH * I_DIM * 2 * C_DIM];
__device__ float g_y [BATCH * T_DIM * C_DIM];

// ---------------------------------------------------------------------------
// bf16 2-split helpers
// ---------------------------------------------------------------------------
__device__ __forceinline__ unsigned pack_bf2(float x, float y) {
    __nv_bfloat162 t = __floats2bfloat162_rn(x, y);   // .x = x (low half, even k)
    return *reinterpret_cast<unsigned*>(&t);
}

__device__ __forceinline__ void split2(float x, float y, unsigned& hi, unsigned& lo) {
    float hx = __bfloat162float(__float2bfloat16(x));
    float hy = __bfloat162float(__float2bfloat16(y));
    hi = pack_bf2(hx, hy);
    lo = pack_bf2(x - hx, y - hy);
}

__device__ __forceinline__ void mma_bf16(float* c,
    unsigned a0, unsigned a1, unsigned a2, unsigned a3,
    unsigned b0, unsigned b1)
{
    asm volatile(
        "mma.sync.aligned.m16n8k16.row.col.f32.bf16.bf16.f32 "
        "{%0,%1,%2,%3},{%4,%5,%6,%7},{%8,%9},{%0,%1,%2,%3};\n"
        : "+f"(c[0]), "+f"(c[1]), "+f"(c[2]), "+f"(c[3])
        : "r"(a0), "r"(a1), "r"(a2), "r"(a3), "r"(b0), "r"(b1));
}

// ---------------------------------------------------------------------------
// GEMM NT (bf16 2-split): C[M,N] = A[M,K] * B[N,K]^T + bias[N]
// Block 128x128x32, 256 threads = 8 warps (2m x 4n), warp tile 64x32.
// smem: packed bf16x2 words, uint2 = (hi,lo), stride 132, XOR swizzle.
// ---------------------------------------------------------------------------
#define BM 128
#define BN 128
#define BK 32
#define MS2 132      // uint2 stride per kw row

// word index for (kw, m): swizzled
__device__ __forceinline__ int sidx(int kw, int m) {
    return kw * MS2 + (m ^ ((kw & 3) << 3));
}

__global__ __launch_bounds__(256) void sgemm_bf16s(
    const float* __restrict__ A, const float* __restrict__ B,
    const float* __restrict__ bias, float* __restrict__ C,
    int M, int N, int K)
{
    __shared__ uint2 sA[16 * MS2];
    __shared__ uint2 sB[16 * MS2];

    const int tid  = threadIdx.x;
    const int m0   = blockIdx.y * BM;
    const int n0   = blockIdx.x * BN;
    const int wid  = tid >> 5;
    const int lane = tid & 31;
    const int g    = lane >> 2;        // 0..7
    const int tig  = lane & 3;         // 0..3
    const int t8   = tig << 3;         // swizzle term (kw&3 == tig for all frag words)
    const int wm   = (wid >> 2) * 64;  // 0,64
    const int wn   = (wid & 3) * 32;   // 0,32,64,96

    // loaders: 32 rows x 8 float4 per pass, 4 passes
    const int lr  = tid >> 3;          // 0..31
    const int lk4 = tid & 7;           // float4 index; k = 4*lk4

    float acc[4][4][4];
#pragma unroll
    for (int i = 0; i < 4; i++)
#pragma unroll
        for (int j = 0; j < 4; j++)
#pragma unroll
            for (int r = 0; r < 4; r++) acc[i][j][r] = 0.f;

    const float* Ag = A + (size_t)(m0 + lr) * K + 4 * lk4;
    const float* Bg = B + (size_t)(n0 + lr) * K + 4 * lk4;

    for (int k0 = 0; k0 < K; k0 += BK) {
        float4 av[4], bv[4];
#pragma unroll
        for (int p = 0; p < 4; p++) {
            av[p] = *(const float4*)(Ag + (size_t)(p * 32) * K + k0);
            bv[p] = *(const float4*)(Bg + (size_t)(p * 32) * K + k0);
        }

        __syncthreads();   // previous iteration's fragment reads done

#pragma unroll
        for (int p = 0; p < 4; p++) {
            const int m = lr + p * 32;
            unsigned h0, l0, h1, l1;
            split2(av[p].x, av[p].y, h0, l0);
            split2(av[p].z, av[p].w, h1, l1);
            sA[sidx(2 * lk4,     m)] = make_uint2(h0, l0);
            sA[sidx(2 * lk4 + 1, m)] = make_uint2(h1, l1);
            split2(bv[p].x, bv[p].y, h0, l0);
            split2(bv[p].z, bv[p].w, h1, l1);
            sB[sidx(2 * lk4,     m)] = make_uint2(h0, l0);
            sB[sidx(2 * lk4 + 1, m)] = make_uint2(h1, l1);
        }

        __syncthreads();

#pragma unroll
        for (int kk2 = 0; kk2 < 2; kk2++) {
            const int kwa = kk2 * 8 + tig;
            uint2 a[4][4];
#pragma unroll
            for (int mt = 0; mt < 4; mt++) {
                const int r = wm + 16 * mt + g;
                a[mt][0] = sA[kwa * MS2 + (r ^ t8)];
                a[mt][1] = sA[kwa * MS2 + ((r + 8) ^ t8)];
                a[mt][2] = sA[(kwa + 4) * MS2 + (r ^ t8)];
                a[mt][3] = sA[(kwa + 4) * MS2 + ((r + 8) ^ t8)];
            }
            uint2 b[4][2];
#pragma unroll
            for (int nt = 0; nt < 4; nt++) {
                const int c = wn + 8 * nt + g;
                b[nt][0] = sB[kwa * MS2 + (c ^ t8)];
                b[nt][1] = sB[(kwa + 4) * MS2 + (c ^ t8)];
            }
#pragma unroll
            for (int mt = 0; mt < 4; mt++)
#pragma unroll
                for (int nt = 0; nt < 4; nt++) {
                    float* cc = acc[mt][nt];
                    mma_bf16(cc, a[mt][0].x, a[mt][1].x, a[mt][2].x, a[mt][3].x,
                                 b[nt][0].x, b[nt][1].x);
                    mma_bf16(cc, a[mt][0].y, a[mt][1].y, a[mt][2].y, a[mt][3].y,
                                 b[nt][0].x, b[nt][1].x);
                    mma_bf16(cc, a[mt][0].x, a[mt][1].x, a[mt][2].x, a[mt][3].x,
                                 b[nt][0].y, b[nt][1].y);
                }
        }
    }

    // epilogue: c0,c1 -> (row g, cols 2tig..+1); c2,c3 -> (row g+8)
#pragma unroll
    for (int mt = 0; mt < 4; mt++) {
        const int r0 = m0 + wm + 16 * mt + g;
#pragma unroll
        for (int nt = 0; nt < 4; nt++) {
            const int cb = n0 + wn + 8 * nt + 2 * tig;
            const float b0 = bias[cb], b1 = bias[cb + 1];
            float2* p0 = (float2*)(C + (size_t)r0 * N + cb);
            float2* p1 = (float2*)(C + (size_t)(r0 + 8) * N + cb);
            *p0 = make_float2(acc[mt][nt][0] + b0, acc[mt][nt][1] + b1);
            *p1 = make_float2(acc[mt][nt][2] + b0, acc[mt][nt][3] + b1);
        }
    }
}

// ---------------------------------------------------------------------------
// Attention (unchanged from R1 — known correct; R4 target)
// ---------------------------------------------------------------------------
#define SQ_STRIDE 65
#define SS_STRIDE 577
#define ST_STRIDE 65
#define ATTN_SMEM_FLOATS (32 * SQ_STRIDE + 32 * SS_STRIDE + 64 * ST_STRIDE + 32)
#define ATTN_SMEM_BYTES  (ATTN_SMEM_FLOATS * 4)

__global__ __launch_bounds__(256) void attn_kernel(
    const float* __restrict__ qb, const float* __restrict__ kvb,
    float* __restrict__ yb)
{
    extern __shared__ float sm[];
    float* sQ = sm;
    float* sS = sQ + 32 * SQ_STRIDE;
    float* sT = sS + 32 * SS_STRIDE;
    float* sL = sT + 64 * ST_STRIDE;

    const int tid = threadIdx.x;
    const int b = blockIdx.z;
    const int h = blockIdx.y;
    const int t0 = blockIdx.x * 32;

    {
        const float* qptr = qb + ((size_t)b * T_DIM + t0) * C_DIM + h * HD;
        for (int idx = tid; idx < 32 * 64; idx += 256) {
            int t = idx >> 6, d = idx & 63;
            sQ[t * SQ_STRIDE + d] = qptr[(size_t)t * C_DIM + d];
        }
    }
    __syncthreads();

    const int tt   = tid >> 4;
    const int ii   = tid & 15;
    const int trow = tt * 2;
    const int icol = ii * 4;

    for (int i0 = 0; i0 < I_DIM; i0 += 64) {
        const float* kptr = kvb + ((size_t)b * I_DIM + i0) * (2 * C_DIM) + h * HD;
        for (int idx = tid; idx < 64 * 64; idx += 256) {
            int i = idx >> 6, d = idx & 63;
            sT[i * ST_STRIDE + d] = kptr[(size_t)i * (2 * C_DIM) + d];
        }
        __syncthreads();

        float a00 = 0.f, a01 = 0.f, a02 = 0.f, a03 = 0.f;
        float a10 = 0.f, a11 = 0.f, a12 = 0.f, a13 = 0.f;
        const float* q0p = &sQ[trow * SQ_STRIDE];
        const float* q1p = &sQ[(trow + 1) * SQ_STRIDE];
        const float* k0p = &sT[(icol + 0) * ST_STRIDE];
        const float* k1p = &sT[(icol + 1) * ST_STRIDE];
        const float* k2p = &sT[(icol + 2) * ST_STRIDE];
        const float* k3p = &sT[(icol + 3) * ST_STRIDE];
#pragma unroll 16
        for (int d = 0; d < 64; d++) {
            float q0 = q0p[d], q1 = q1p[d];
            float k0 = k0p[d], k1 = k1p[d], k2 = k2p[d], k3 = k3p[d];
            a00 += q0 * k0; a01 += q0 * k1; a02 += q0 * k2; a03 += q0 * k3;
            a10 += q1 * k0; a11 += q1 * k1; a12 += q1 * k2; a13 += q1 * k3;
        }
        float* s0 = &sS[trow * SS_STRIDE + i0 + icol];
        float* s1 = &sS[(trow + 1) * SS_STRIDE + i0 + icol];
        s0[0] = a00 * 0.125f; s0[1] = a01 * 0.125f; s0[2] = a02 * 0.125f; s0[3] = a03 * 0.125f;
        s1[0] = a10 * 0.125f; s1[1] = a11 * 0.125f; s1[2] = a12 * 0.125f; s1[3] = a13 * 0.125f;
        __syncthreads();
    }

    {
        const int row = tid >> 3, gg = tid & 7;
        float* sr = &sS[row * SS_STRIDE];
        float m = -1e30f;
        for (int i = gg; i < I_DIM; i += 8) m = fmaxf(m, sr[i]);
        m = fmaxf(m, __shfl_xor_sync(0xffffffffu, m, 1));
        m = fmaxf(m, __shfl_xor_sync(0xffffffffu, m, 2));
        m = fmaxf(m, __shfl_xor_sync(0xffffffffu, m, 4));
        float s = 0.f;
        for (int i = gg; i < I_DIM; i += 8) {
            float e = __expf(sr[i] - m);
            sr[i] = e;
            s += e;
        }
        s += __shfl_xor_sync(0xffffffffu, s, 1);
        s += __shfl_xor_sync(0xffffffffu, s, 2);
        s += __shfl_xor_sync(0xffffffffu, s, 4);
        if (gg == 0) sL[row] = s;
    }
    __syncthreads();

    float y00 = 0.f, y01 = 0.f, y02 = 0.f, y03 = 0.f;
    float y10 = 0.f, y11 = 0.f, y12 = 0.f, y13 = 0.f;
    for (int i0 = 0; i0 < I_DIM; i0 += 64) {
        const float* vptr = kvb + ((size_t)b * I_DIM + i0) * (2 * C_DIM) + C_DIM + h * HD;
        for (int idx = tid; idx < 64 * 64; idx += 256) {
            int i = idx >> 6, d = idx & 63;
            sT[i * ST_STRIDE + d] = vptr[(size_t)i * (2 * C_DIM) + d];
        }
        __syncthreads();

        const float* p0p = &sS[trow * SS_STRIDE + i0];
        const float* p1p = &sS[(trow + 1) * SS_STRIDE + i0];
#pragma unroll 8
        for (int i = 0; i < 64; i++) {
            float p0 = p0p[i], p1 = p1p[i];
            const float* vp = &sT[i * ST_STRIDE + icol];
            float v0 = vp[0], v1 = vp[1], v2 = vp[2], v3 = vp[3];
            y00 += p0 * v0; y01 += p0 * v1; y02 += p0 * v2; y03 += p0 * v3;
            y10 += p1 * v0; y11 += p1 * v1; y12 += p1 * v2; y13 += p1 * v3;
        }
        __syncthreads();
    }

    const float inv0 = 1.0f / sL[trow];
    const float inv1 = 1.0f / sL[trow + 1];
    float* y0p = yb + ((size_t)b * T_DIM + t0 + trow) * C_DIM + h * HD + icol;
    float* y1p = y0p + C_DIM;
    y0p[0] = y00 * inv0; y0p[1] = y01 * inv0; y0p[2] = y02 * inv0; y0p[3] = y03 * inv0;
    y1p[0] = y10 * inv1; y1p[1] = y11 * inv1; y1p[2] = y12 * inv1; y1p[3] = y13 * inv1;
}

// ---------------------------------------------------------------------------
// Launch
// ---------------------------------------------------------------------------
extern "C" void kernel_launch(void* const* d_in, const int* in_sizes, int n_in,
                              void* d_out, int out_size)
{
    const float* x   = (const float*)d_in[0];
    const float* enc = (const float*)d_in[1];
    const float* Wq  = (const float*)d_in[2];
    const float* bq  = (const float*)d_in[3];
    const float* Wkv = (const float*)d_in[4];
    const float* bkv = (const float*)d_in[5];
    const float* Wo  = (const float*)d_in[6];
    const float* bo  = (const float*)d_in[7];
    float* out = (float*)d_out;

    float *qp, *kvp, *yp;
    cudaGetSymbolAddress((void**)&qp,  g_q);
    cudaGetSymbolAddress((void**)&kvp, g_kv);
    cudaGetSymbolAddress((void**)&yp,  g_y);

    cudaFuncSetAttribute(attn_kernel,
                         cudaFuncAttributeMaxDynamicSharedMemorySize,
                         ATTN_SMEM_BYTES);

    // Q = x @ Wq^T + bq           : M=8192, N=1024, K=1024
    sgemm_bf16s<<<dim3(C_DIM / BN, (BATCH * T_DIM) / BM), 256>>>(
        x, Wq, bq, qp, BATCH * T_DIM, C_DIM, C_DIM);

    // KV = enc @ Wkv^T + bkv      : M=4608, N=2048, K=1024
    sgemm_bf16s<<<dim3((2 * C_DIM) / BN, (BATCH * I_DIM) / BM), 256>>>(
        enc, Wkv, bkv, kvp, BATCH * I_DIM, 2 * C_DIM, C_DIM);

    // attention -> y
    attn_kernel<<<dim3(T_DIM / 32, N_HEAD, BATCH), 256, ATTN_SMEM_BYTES>>>(
        qp, kvp, yp);

    // out = y @ Wo^T + bo         : M=8192, N=1024, K=1024
    sgemm_bf16s<<<dim3(C_DIM / BN, (BATCH * T_DIM) / BM), 256>>>(
        yp, Wo, bo, out, BATCH * T_DIM, C_DIM, C_DIM);
}

// round 5
// speedup vs baseline: 2.7624x; 1.7947x over previous
#include <cuda_runtime.h>
#include <cuda_bf16.h>
#include <math.h>

// Problem constants
#define BATCH  8
#define T_DIM  1024
#define I_DIM  576
#define C_DIM  1024
#define N_HEAD 16
#define HD     64

// ---------------------------------------------------------------------------
// Scratch: split-bf16 planes. uint2 = (bf16x2 hi, bf16x2 lo), pairs along last
// dim: word w of a row covers elements (2w, 2w+1).
// ---------------------------------------------------------------------------
__device__ uint2 g_xs  [BATCH * T_DIM * C_DIM / 2];
__device__ uint2 g_es  [BATCH * I_DIM * C_DIM / 2];
__device__ uint2 g_wqs [C_DIM * C_DIM / 2];
__device__ uint2 g_wkvs[2 * C_DIM * C_DIM / 2];
__device__ uint2 g_wos [C_DIM * C_DIM / 2];
__device__ uint2 g_qs  [BATCH * T_DIM * C_DIM / 2];
__device__ uint2 g_kvs [BATCH * I_DIM * 2 * C_DIM / 2];
__device__ uint2 g_ys  [BATCH * T_DIM * C_DIM / 2];

// ---------------------------------------------------------------------------
// helpers
// ---------------------------------------------------------------------------
__device__ __forceinline__ unsigned pack_bf2(float x, float y) {
    __nv_bfloat162 t = __floats2bfloat162_rn(x, y);   // .x = low half
    return *reinterpret_cast<unsigned*>(&t);
}
__device__ __forceinline__ uint2 splitw(float x, float y) {
    float hx = __bfloat162float(__float2bfloat16(x));
    float hy = __bfloat162float(__float2bfloat16(y));
    return make_uint2(pack_bf2(hx, hy), pack_bf2(x - hx, y - hy));
}
__device__ __forceinline__ unsigned prmt(unsigned a, unsigned b, unsigned s) {
    unsigned d;
    asm("prmt.b32 %0,%1,%2,%3;" : "=r"(d) : "r"(a), "r"(b), "r"(s));
    return d;
}
__device__ __forceinline__ void mma_bf16(float* c,
    unsigned a0, unsigned a1, unsigned a2, unsigned a3,
    unsigned b0, unsigned b1)
{
    asm volatile(
        "mma.sync.aligned.m16n8k16.row.col.f32.bf16.bf16.f32 "
        "{%0,%1,%2,%3},{%4,%5,%6,%7},{%8,%9},{%0,%1,%2,%3};\n"
        : "+f"(c[0]), "+f"(c[1]), "+f"(c[2]), "+f"(c[3])
        : "r"(a0), "r"(a1), "r"(a2), "r"(a3), "r"(b0), "r"(b1));
}
// issue the 3-term split product: hi*hi + lo*hi + hi*lo
__device__ __forceinline__ void mma_split(float* c, const uint2 a[4], const uint2 b[2]) {
    mma_bf16(c, a[0].x, a[1].x, a[2].x, a[3].x, b[0].x, b[1].x);
    mma_bf16(c, a[0].y, a[1].y, a[2].y, a[3].y, b[0].x, b[1].x);
    mma_bf16(c, a[0].x, a[1].x, a[2].x, a[3].x, b[0].y, b[1].y);
}

// ---------------------------------------------------------------------------
// conversion: fp32 tensor -> split planes (pairs along last dim, dim even)
// ---------------------------------------------------------------------------
__global__ __launch_bounds__(256) void convert_split(
    const float2* __restrict__ src, uint2* __restrict__ dst, int n)
{
    int i = blockIdx.x * 256 + threadIdx.x;
    if (i < n) { float2 v = src[i]; dst[i] = splitw(v.x, v.y); }
}

// ---------------------------------------------------------------------------
// GEMM NT on split planes: C[M,N] = A[M,K] B[N,K]^T + bias
// Block 128x128, stage = k16 (8 words), double-buffered. 8 warps (2m x 4n),
// warp tile 64x32, micro 4x4 m16n8 tiles. 3 HMMA per tile per stage.
// ---------------------------------------------------------------------------
#define MS2 132
__device__ __forceinline__ int sidx(int kw, int m) {
    return kw * MS2 + (m ^ ((kw & 3) << 3));
}
#define STG (8 * MS2)   // uint2 per stage buffer

template<bool SPLIT_OUT>
__global__ __launch_bounds__(256) void gemm_split(
    const uint2* __restrict__ AS, const uint2* __restrict__ BS,
    const float* __restrict__ bias, float* __restrict__ Cf,
    uint2* __restrict__ Cs, int M, int N, int KW)
{
    __shared__ uint2 sm[4 * STG];   // sA[2], sB[2]

    const int tid  = threadIdx.x;
    const int m0   = blockIdx.y * 128;
    const int n0   = blockIdx.x * 128;
    const int wid  = tid >> 5;
    const int lane = tid & 31;
    const int g    = lane >> 2;
    const int tig  = lane & 3;
    const int t8   = tig << 3;
    const int wm   = (wid >> 2) * 64;
    const int wn   = (wid & 3) * 32;

    const int lr = tid >> 1;          // 0..127
    const int jb = (tid & 1) * 4;     // word offset 0 or 4

    const uint4* Ag = (const uint4*)(AS + (size_t)(m0 + lr) * KW + jb);
    const uint4* Bg = (const uint4*)(BS + (size_t)(n0 + lr) * KW + jb);
    // stage s starts at word s*8 -> uint4 offset s*4

    float acc[4][4][4];
#pragma unroll
    for (int i = 0; i < 4; i++)
#pragma unroll
        for (int j = 0; j < 4; j++)
#pragma unroll
            for (int r = 0; r < 4; r++) acc[i][j][r] = 0.f;

    const int NS = KW >> 3;
    uint4 a0, a1, b0, b1;

    // prologue: stage 0
    a0 = Ag[0]; a1 = Ag[1]; b0 = Bg[0]; b1 = Bg[1];
    {
        uint2* dA = sm;             uint2* dB = sm + 2 * STG;
        dA[sidx(jb + 0, lr)] = make_uint2(a0.x, a0.y);
        dA[sidx(jb + 1, lr)] = make_uint2(a0.z, a0.w);
        dA[sidx(jb + 2, lr)] = make_uint2(a1.x, a1.y);
        dA[sidx(jb + 3, lr)] = make_uint2(a1.z, a1.w);
        dB[sidx(jb + 0, lr)] = make_uint2(b0.x, b0.y);
        dB[sidx(jb + 1, lr)] = make_uint2(b0.z, b0.w);
        dB[sidx(jb + 2, lr)] = make_uint2(b1.x, b1.y);
        dB[sidx(jb + 3, lr)] = make_uint2(b1.z, b1.w);
    }
    __syncthreads();

    for (int s = 0; s < NS; s++) {
        const int cur = s & 1;
        if (s + 1 < NS) {
            const uint4* ap = Ag + (size_t)(s + 1) * 4;
            const uint4* bp = Bg + (size_t)(s + 1) * 4;
            a0 = ap[0]; a1 = ap[1]; b0 = bp[0]; b1 = bp[1];
        }

        const uint2* sa = sm + cur * STG;
        const uint2* sb = sm + 2 * STG + cur * STG;

        uint2 af[4][4];
#pragma unroll
        for (int mt = 0; mt < 4; mt++) {
            const int r = wm + 16 * mt + g;
            af[mt][0] = sa[tig * MS2 + (r ^ t8)];
            af[mt][1] = sa[tig * MS2 + ((r + 8) ^ t8)];
            af[mt][2] = sa[(tig + 4) * MS2 + (r ^ t8)];
            af[mt][3] = sa[(tig + 4) * MS2 + ((r + 8) ^ t8)];
        }
        uint2 bf[4][2];
#pragma unroll
        for (int nt = 0; nt < 4; nt++) {
            const int c = wn + 8 * nt + g;
            bf[nt][0] = sb[tig * MS2 + (c ^ t8)];
            bf[nt][1] = sb[(tig + 4) * MS2 + (c ^ t8)];
        }
#pragma unroll
        for (int mt = 0; mt < 4; mt++)
#pragma unroll
            for (int nt = 0; nt < 4; nt++)
                mma_split(acc[mt][nt], af[mt], bf[nt]);

        if (s + 1 < NS) {
            uint2* dA = sm + ((s + 1) & 1) * STG;
            uint2* dB = sm + 2 * STG + ((s + 1) & 1) * STG;
            dA[sidx(jb + 0, lr)] = make_uint2(a0.x, a0.y);
            dA[sidx(jb + 1, lr)] = make_uint2(a0.z, a0.w);
            dA[sidx(jb + 2, lr)] = make_uint2(a1.x, a1.y);
            dA[sidx(jb + 3, lr)] = make_uint2(a1.z, a1.w);
            dB[sidx(jb + 0, lr)] = make_uint2(b0.x, b0.y);
            dB[sidx(jb + 1, lr)] = make_uint2(b0.z, b0.w);
            dB[sidx(jb + 2, lr)] = make_uint2(b1.x, b1.y);
            dB[sidx(jb + 3, lr)] = make_uint2(b1.z, b1.w);
        }
        __syncthreads();
    }

    // epilogue
#pragma unroll
    for (int mt = 0; mt < 4; mt++) {
        const int r0 = m0 + wm + 16 * mt + g;
#pragma unroll
        for (int nt = 0; nt < 4; nt++) {
            const int cb = n0 + wn + 8 * nt + 2 * tig;
            const float v0 = bias[cb], v1 = bias[cb + 1];
            if (SPLIT_OUT) {
                Cs[(size_t)r0 * (N >> 1) + (cb >> 1)] =
                    splitw(acc[mt][nt][0] + v0, acc[mt][nt][1] + v1);
                Cs[(size_t)(r0 + 8) * (N >> 1) + (cb >> 1)] =
                    splitw(acc[mt][nt][2] + v0, acc[mt][nt][3] + v1);
            } else {
                *(float2*)(Cf + (size_t)r0 * N + cb) =
                    make_float2(acc[mt][nt][0] + v0, acc[mt][nt][1] + v1);
                *(float2*)(Cf + (size_t)(r0 + 8) * N + cb) =
                    make_float2(acc[mt][nt][2] + v0, acc[mt][nt][3] + v1);
            }
        }
    }
}

// ---------------------------------------------------------------------------
// Attention via split-mma. Block = (64 t-rows, head h, batch b). 256 threads,
// 8 warps (4m x 2n), warp tile 16t x 32.
// Phase1: S = QK^T * 0.125 per 64-i chunk -> sS fp32 [64][SSTR]
// Phase2: two-pass softmax (exp stored back, 1/sum folded later)
// Phase3: P split on the fly -> sPP, V repacked i-pairwise -> sV, Y += P V
// ---------------------------------------------------------------------------
#define SSTR 586
#define AQS  68
__device__ __forceinline__ int aidx(int kw, int m) {
    return kw * AQS + (m ^ ((kw & 3) << 3));
}
#define ATTN_BYTES (64 * SSTR * 4 + 2 * 32 * AQS * 8 + 256)

__global__ __launch_bounds__(256) void attn_mma(
    const uint2* __restrict__ qs, const uint2* __restrict__ kvs,
    uint2* __restrict__ ys)
{
    extern __shared__ char smraw[];
    float* sS  = (float*)smraw;                       // [64][SSTR]
    uint2* sQ  = (uint2*)(smraw + 64 * SSTR * 4);     // 32*AQS  (later: sPP)
    uint2* sKV = sQ + 32 * AQS;                       // 32*AQS  (K then V chunks)
    float* sInv = (float*)(sKV + 32 * AQS);           // [64]

    const int tid  = threadIdx.x;
    const int wid  = tid >> 5;
    const int lane = tid & 31;
    const int g    = lane >> 2;
    const int tig  = lane & 3;
    const int t8   = tig << 3;
    const int wm   = (wid >> 1) * 16;
    const int wn   = (wid & 1) * 32;

    const int b  = blockIdx.z;
    const int h  = blockIdx.y;
    const int t0 = blockIdx.x * 64;

    // load Q tile: 64 rows x 32 words
#pragma unroll
    for (int w = 0; w < 8; w++) {
        int Wd = tid + 256 * w;
        int r = Wd >> 5, dw = Wd & 31;
        sQ[aidx(dw, r)] = qs[(size_t)(b * T_DIM + t0 + r) * 512 + h * 32 + dw];
    }

    // ---- Phase 1 ----
    for (int c = 0; c < 9; c++) {
        const int i0 = c * 64;
#pragma unroll
        for (int w = 0; w < 8; w++) {
            int Wd = tid + 256 * w;
            int r = Wd >> 5, dw = Wd & 31;
            sKV[aidx(dw, r)] = kvs[(size_t)(b * I_DIM + i0 + r) * 1024 + h * 32 + dw];
        }
        __syncthreads();

        float acc[4][4];
#pragma unroll
        for (int nt = 0; nt < 4; nt++)
#pragma unroll
            for (int r = 0; r < 4; r++) acc[nt][r] = 0.f;

#pragma unroll
        for (int ks = 0; ks < 4; ks++) {
            const int kwa = 8 * ks + tig;
            uint2 af[4];
            af[0] = sQ[kwa * AQS + ((wm + g) ^ t8)];
            af[1] = sQ[kwa * AQS + ((wm + g + 8) ^ t8)];
            af[2] = sQ[(kwa + 4) * AQS + ((wm + g) ^ t8)];
            af[3] = sQ[(kwa + 4) * AQS + ((wm + g + 8) ^ t8)];
#pragma unroll
            for (int nt = 0; nt < 4; nt++) {
                const int cc = wn + 8 * nt + g;
                uint2 bf2[2];
                bf2[0] = sKV[kwa * AQS + (cc ^ t8)];
                bf2[1] = sKV[(kwa + 4) * AQS + (cc ^ t8)];
                mma_split(acc[nt], af, bf2);
            }
        }
#pragma unroll
        for (int nt = 0; nt < 4; nt++) {
            const int col = i0 + wn + 8 * nt + 2 * tig;
            *(float2*)&sS[(wm + g) * SSTR + col] =
                make_float2(acc[nt][0] * 0.125f, acc[nt][1] * 0.125f);
            *(float2*)&sS[(wm + g + 8) * SSTR + col] =
                make_float2(acc[nt][2] * 0.125f, acc[nt][3] * 0.125f);
        }
        __syncthreads();
    }

    // ---- Phase 2: softmax stats; store exp back ----
    {
        const int row = tid >> 2, gg = tid & 3;
        float* sr = sS + row * SSTR;
        float m = -1e30f;
        for (int i = gg; i < I_DIM; i += 4) m = fmaxf(m, sr[i]);
        m = fmaxf(m, __shfl_xor_sync(0xffffffffu, m, 1));
        m = fmaxf(m, __shfl_xor_sync(0xffffffffu, m, 2));
        float s = 0.f;
        for (int i = gg; i < I_DIM; i += 4) {
            float e = __expf(sr[i] - m);
            sr[i] = e;
            s += e;
        }
        s += __shfl_xor_sync(0xffffffffu, s, 1);
        s += __shfl_xor_sync(0xffffffffu, s, 2);
        if (gg == 0) sInv[row] = 1.0f / s;
    }
    __syncthreads();

    // ---- Phase 3: Y = (P/sum) V ----
    float ya[4][4];
#pragma unroll
    for (int nt = 0; nt < 4; nt++)
#pragma unroll
        for (int r = 0; r < 4; r++) ya[nt][r] = 0.f;

    for (int c = 0; c < 9; c++) {
        const int i0 = c * 64;
        // P chunk -> sQ (as sPP): word (iw, t) covers i = i0+2iw, i0+2iw+1
#pragma unroll
        for (int w = 0; w < 8; w++) {
            int Wd = tid + 256 * w;
            int iw = Wd >> 6, t = Wd & 63;
            float2 sv = *(float2*)&sS[t * SSTR + i0 + 2 * iw];
            float inv = sInv[t];
            sQ[aidx(iw, t)] = splitw(sv.x * inv, sv.y * inv);
        }
        // V chunk -> sKV: word (iw, d) = (v[2iw][d], v[2iw+1][d]) pairs
#pragma unroll
        for (int p = 0; p < 4; p++) {
            int P = tid + 256 * p;
            int iw = P >> 5, dv = P & 31;
            uint2 r0 = kvs[(size_t)(b * I_DIM + i0 + 2 * iw) * 1024 + 512 + h * 32 + dv];
            uint2 r1 = kvs[(size_t)(b * I_DIM + i0 + 2 * iw + 1) * 1024 + 512 + h * 32 + dv];
            sKV[aidx(iw, 2 * dv)]     = make_uint2(prmt(r0.x, r1.x, 0x5410),
                                                   prmt(r0.y, r1.y, 0x5410));
            sKV[aidx(iw, 2 * dv + 1)] = make_uint2(prmt(r0.x, r1.x, 0x7632),
                                                   prmt(r0.y, r1.y, 0x7632));
        }
        __syncthreads();

#pragma unroll
        for (int ks = 0; ks < 4; ks++) {
            const int kwa = 8 * ks + tig;
            uint2 af[4];
            af[0] = sQ[kwa * AQS + ((wm + g) ^ t8)];
            af[1] = sQ[kwa * AQS + ((wm + g + 8) ^ t8)];
            af[2] = sQ[(kwa + 4) * AQS + ((wm + g) ^ t8)];
            af[3] = sQ[(kwa + 4) * AQS + ((wm + g + 8) ^ t8)];
#pragma unroll
            for (int nt = 0; nt < 4; nt++) {
                const int cc = wn + 8 * nt + g;
                uint2 bf2[2];
                bf2[0] = sKV[kwa * AQS + (cc ^ t8)];
                bf2[1] = sKV[(kwa + 4) * AQS + (cc ^ t8)];
                mma_split(ya[nt], af, bf2);
            }
        }
        __syncthreads();
    }

    // epilogue: write split y
#pragma unroll
    for (int nt = 0; nt < 4; nt++) {
        const int col = wn + 8 * nt + 2 * tig;       // d-local, even
        const int cw  = h * 32 + (col >> 1);
        const size_t r0 = (size_t)(b * T_DIM + t0 + wm + g);
        ys[r0 * 512 + cw]       = splitw(ya[nt][0], ya[nt][1]);
        ys[(r0 + 8) * 512 + cw] = splitw(ya[nt][2], ya[nt][3]);
    }
}

// ---------------------------------------------------------------------------
// Launch
// ---------------------------------------------------------------------------
extern "C" void kernel_launch(void* const* d_in, const int* in_sizes, int n_in,
                              void* d_out, int out_size)
{
    const float* x   = (const float*)d_in[0];
    const float* enc = (const float*)d_in[1];
    const float* Wq  = (const float*)d_in[2];
    const float* bq  = (const float*)d_in[3];
    const float* Wkv = (const float*)d_in[4];
    const float* bkv = (const float*)d_in[5];
    const float* Wo  = (const float*)d_in[6];
    const float* bo  = (const float*)d_in[7];
    float* out = (float*)d_out;

    uint2 *xs, *es, *wqs, *wkvs, *wos, *qsp, *kvsp, *ysp;
    cudaGetSymbolAddress((void**)&xs,   g_xs);
    cudaGetSymbolAddress((void**)&es,   g_es);
    cudaGetSymbolAddress((void**)&wqs,  g_wqs);
    cudaGetSymbolAddress((void**)&wkvs, g_wkvs);
    cudaGetSymbolAddress((void**)&wos,  g_wos);
    cudaGetSymbolAddress((void**)&qsp,  g_qs);
    cudaGetSymbolAddress((void**)&kvsp, g_kvs);
    cudaGetSymbolAddress((void**)&ysp,  g_ys);

    cudaFuncSetAttribute(attn_mma,
                         cudaFuncAttributeMaxDynamicSharedMemorySize, ATTN_BYTES);

    // conversions (fp32 -> split planes)
    {
        int n;
        n = BATCH * T_DIM * C_DIM / 2;
        convert_split<<<(n + 255) / 256, 256>>>((const float2*)x, xs, n);
        n = BATCH * I_DIM * C_DIM / 2;
        convert_split<<<(n + 255) / 256, 256>>>((const float2*)enc, es, n);
        n = C_DIM * C_DIM / 2;
        convert_split<<<(n + 255) / 256, 256>>>((const float2*)Wq, wqs, n);
        n = 2 * C_DIM * C_DIM / 2;
        convert_split<<<(n + 255) / 256, 256>>>((const float2*)Wkv, wkvs, n);
        n = C_DIM * C_DIM / 2;
        convert_split<<<(n + 255) / 256, 256>>>((const float2*)Wo, wos, n);
    }

    // Q = x Wq^T + bq  -> split q
    gemm_split<true><<<dim3(C_DIM / 128, BATCH * T_DIM / 128), 256>>>(
        xs, wqs, bq, nullptr, qsp, BATCH * T_DIM, C_DIM, C_DIM / 2);

    // KV = enc Wkv^T + bkv -> split kv
    gemm_split<true><<<dim3(2 * C_DIM / 128, BATCH * I_DIM / 128), 256>>>(
        es, wkvs, bkv, nullptr, kvsp, BATCH * I_DIM, 2 * C_DIM, C_DIM / 2);

    // attention -> split y
    attn_mma<<<dim3(T_DIM / 64, N_HEAD, BATCH), 256, ATTN_BYTES>>>(qsp, kvsp, ysp);

    // out = y Wo^T + bo  (fp32)
    gemm_split<false><<<dim3(C_DIM / 128, BATCH * T_DIM / 128), 256>>>(
        ysp, wos, bo, out, nullptr, BATCH * T_DIM, C_DIM, C_DIM / 2);
}

// round 8
// speedup vs baseline: 3.2264x; 1.1680x over previous
#include <cuda_runtime.h>
#include <cuda_bf16.h>
#include <math.h>

// Problem constants
#define BATCH  8
#define T_DIM  1024
#define I_DIM  576
#define C_DIM  1024
#define N_HEAD 16
#define HD     64

// ---------------------------------------------------------------------------
// Scratch: split-bf16 planes. uint2 = (bf16x2 hi, bf16x2 lo), pairs along last
// dim: word w of a row covers elements (2w, 2w+1).
// ---------------------------------------------------------------------------
__device__ uint2 g_xs  [BATCH * T_DIM * C_DIM / 2];
__device__ uint2 g_es  [BATCH * I_DIM * C_DIM / 2];
__device__ uint2 g_wqs [C_DIM * C_DIM / 2];
__device__ uint2 g_wkvs[2 * C_DIM * C_DIM / 2];
__device__ uint2 g_wos [C_DIM * C_DIM / 2];
__device__ uint2 g_qs  [BATCH * T_DIM * C_DIM / 2];
__device__ uint2 g_kvs [BATCH * I_DIM * 2 * C_DIM / 2];
__device__ uint2 g_ys  [BATCH * T_DIM * C_DIM / 2];

// ---------------------------------------------------------------------------
// helpers
// ---------------------------------------------------------------------------
__device__ __forceinline__ unsigned pack_bf2(float x, float y) {
    __nv_bfloat162 t = __floats2bfloat162_rn(x, y);   // .x = low half
    return *reinterpret_cast<unsigned*>(&t);
}
__device__ __forceinline__ uint2 splitw(float x, float y) {
    float hx = __bfloat162float(__float2bfloat16(x));
    float hy = __bfloat162float(__float2bfloat16(y));
    return make_uint2(pack_bf2(hx, hy), pack_bf2(x - hx, y - hy));
}
__device__ __forceinline__ unsigned prmt(unsigned a, unsigned b, unsigned s) {
    unsigned d;
    asm("prmt.b32 %0,%1,%2,%3;" : "=r"(d) : "r"(a), "r"(b), "r"(s));
    return d;
}
__device__ __forceinline__ void mma_bf16(float* c,
    unsigned a0, unsigned a1, unsigned a2, unsigned a3,
    unsigned b0, unsigned b1)
{
    asm volatile(
        "mma.sync.aligned.m16n8k16.row.col.f32.bf16.bf16.f32 "
        "{%0,%1,%2,%3},{%4,%5,%6,%7},{%8,%9},{%0,%1,%2,%3};\n"
        : "+f"(c[0]), "+f"(c[1]), "+f"(c[2]), "+f"(c[3])
        : "r"(a0), "r"(a1), "r"(a2), "r"(a3), "r"(b0), "r"(b1));
}
__device__ __forceinline__ void mma_split(float* c, const uint2 a[4], const uint2 b[2]) {
    mma_bf16(c, a[0].x, a[1].x, a[2].x, a[3].x, b[0].x, b[1].x);
    mma_bf16(c, a[0].y, a[1].y, a[2].y, a[3].y, b[0].x, b[1].x);
    mma_bf16(c, a[0].x, a[1].x, a[2].x, a[3].x, b[0].y, b[1].y);
}

// ---------------------------------------------------------------------------
// conversion: fp32 tensor -> split planes
// ---------------------------------------------------------------------------
__global__ __launch_bounds__(256) void convert_split(
    const float2* __restrict__ src, uint2* __restrict__ dst, int n)
{
    int i = blockIdx.x * 256 + threadIdx.x;
    if (i < n) { float2 v = src[i]; dst[i] = splitw(v.x, v.y); }
}

// ---------------------------------------------------------------------------
// GEMM NT on split planes (unchanged from R5)
// ---------------------------------------------------------------------------
#define MS2 132
__device__ __forceinline__ int sidx(int kw, int m) {
    return kw * MS2 + (m ^ ((kw & 3) << 3));
}
#define STG (8 * MS2)

template<bool SPLIT_OUT>
__global__ __launch_bounds__(256) void gemm_split(
    const uint2* __restrict__ AS, const uint2* __restrict__ BS,
    const float* __restrict__ bias, float* __restrict__ Cf,
    uint2* __restrict__ Cs, int M, int N, int KW)
{
    __shared__ uint2 sm[4 * STG];

    const int tid  = threadIdx.x;
    const int m0   = blockIdx.y * 128;
    const int n0   = blockIdx.x * 128;
    const int wid  = tid >> 5;
    const int lane = tid & 31;
    const int g    = lane >> 2;
    const int tig  = lane & 3;
    const int t8   = tig << 3;
    const int wm   = (wid >> 2) * 64;
    const int wn   = (wid & 3) * 32;

    const int lr = tid >> 1;
    const int jb = (tid & 1) * 4;

    const uint4* Ag = (const uint4*)(AS + (size_t)(m0 + lr) * KW + jb);
    const uint4* Bg = (const uint4*)(BS + (size_t)(n0 + lr) * KW + jb);

    float acc[4][4][4];
#pragma unroll
    for (int i = 0; i < 4; i++)
#pragma unroll
        for (int j = 0; j < 4; j++)
#pragma unroll
            for (int r = 0; r < 4; r++) acc[i][j][r] = 0.f;

    const int NS = KW >> 3;
    uint4 a0, a1, b0, b1;

    a0 = Ag[0]; a1 = Ag[1]; b0 = Bg[0]; b1 = Bg[1];
    {
        uint2* dA = sm;             uint2* dB = sm + 2 * STG;
        dA[sidx(jb + 0, lr)] = make_uint2(a0.x, a0.y);
        dA[sidx(jb + 1, lr)] = make_uint2(a0.z, a0.w);
        dA[sidx(jb + 2, lr)] = make_uint2(a1.x, a1.y);
        dA[sidx(jb + 3, lr)] = make_uint2(a1.z, a1.w);
        dB[sidx(jb + 0, lr)] = make_uint2(b0.x, b0.y);
        dB[sidx(jb + 1, lr)] = make_uint2(b0.z, b0.w);
        dB[sidx(jb + 2, lr)] = make_uint2(b1.x, b1.y);
        dB[sidx(jb + 3, lr)] = make_uint2(b1.z, b1.w);
    }
    __syncthreads();

    for (int s = 0; s < NS; s++) {
        const int cur = s & 1;
        if (s + 1 < NS) {
            const uint4* ap = Ag + (size_t)(s + 1) * 4;
            const uint4* bp = Bg + (size_t)(s + 1) * 4;
            a0 = ap[0]; a1 = ap[1]; b0 = bp[0]; b1 = bp[1];
        }

        const uint2* sa = sm + cur * STG;
        const uint2* sb = sm + 2 * STG + cur * STG;

        uint2 af[4][4];
#pragma unroll
        for (int mt = 0; mt < 4; mt++) {
            const int r = wm + 16 * mt + g;
            af[mt][0] = sa[tig * MS2 + (r ^ t8)];
            af[mt][1] = sa[tig * MS2 + ((r + 8) ^ t8)];
            af[mt][2] = sa[(tig + 4) * MS2 + (r ^ t8)];
            af[mt][3] = sa[(tig + 4) * MS2 + ((r + 8) ^ t8)];
        }
        uint2 bf[4][2];
#pragma unroll
        for (int nt = 0; nt < 4; nt++) {
            const int c = wn + 8 * nt + g;
            bf[nt][0] = sb[tig * MS2 + (c ^ t8)];
            bf[nt][1] = sb[(tig + 4) * MS2 + (c ^ t8)];
        }
#pragma unroll
        for (int mt = 0; mt < 4; mt++)
#pragma unroll
            for (int nt = 0; nt < 4; nt++)
                mma_split(acc[mt][nt], af[mt], bf[nt]);

        if (s + 1 < NS) {
            uint2* dA = sm + ((s + 1) & 1) * STG;
            uint2* dB = sm + 2 * STG + ((s + 1) & 1) * STG;
            dA[sidx(jb + 0, lr)] = make_uint2(a0.x, a0.y);
            dA[sidx(jb + 1, lr)] = make_uint2(a0.z, a0.w);
            dA[sidx(jb + 2, lr)] = make_uint2(a1.x, a1.y);
            dA[sidx(jb + 3, lr)] = make_uint2(a1.z, a1.w);
            dB[sidx(jb + 0, lr)] = make_uint2(b0.x, b0.y);
            dB[sidx(jb + 1, lr)] = make_uint2(b0.z, b0.w);
            dB[sidx(jb + 2, lr)] = make_uint2(b1.x, b1.y);
            dB[sidx(jb + 3, lr)] = make_uint2(b1.z, b1.w);
        }
        __syncthreads();
    }

#pragma unroll
    for (int mt = 0; mt < 4; mt++) {
        const int r0 = m0 + wm + 16 * mt + g;
#pragma unroll
        for (int nt = 0; nt < 4; nt++) {
            const int cb = n0 + wn + 8 * nt + 2 * tig;
            const float v0 = bias[cb], v1 = bias[cb + 1];
            if (SPLIT_OUT) {
                Cs[(size_t)r0 * (N >> 1) + (cb >> 1)] =
                    splitw(acc[mt][nt][0] + v0, acc[mt][nt][1] + v1);
                Cs[(size_t)(r0 + 8) * (N >> 1) + (cb >> 1)] =
                    splitw(acc[mt][nt][2] + v0, acc[mt][nt][3] + v1);
            } else {
                *(float2*)(Cf + (size_t)r0 * N + cb) =
                    make_float2(acc[mt][nt][0] + v0, acc[mt][nt][1] + v1);
                *(float2*)(Cf + (size_t)(r0 + 8) * N + cb) =
                    make_float2(acc[mt][nt][2] + v0, acc[mt][nt][3] + v1);
            }
        }
    }
}

// ---------------------------------------------------------------------------
// Flash attention via split-mma, register-resident S->P chaining.
// Block = 128 t-rows x (b,h). 8 warps, warp w owns rows [16w, 16w+16).
// Per 64-i chunk: S = QK^T (C-frags), online softmax in regs (quad shuffles),
// P fragments built in regs (C->A identity mapping), Y += P V.
// ---------------------------------------------------------------------------
#define AQ2 136   // sQ stride (uint2)
#define AK2 68    // sK/sV stride (uint2)
__device__ __forceinline__ int qidx(int kw, int r) {
    return kw * AQ2 + (r ^ ((kw & 3) << 3));
}
__device__ __forceinline__ int kidx(int kw, int r) {
    return kw * AK2 + (r ^ ((kw & 3) << 3));
}
#define ATTN_BYTES ((32 * AQ2 + 2 * 32 * AK2) * 8)   // ~69.6 KB

__global__ __launch_bounds__(256) void attn_flash(
    const uint2* __restrict__ qs, const uint2* __restrict__ kvs,
    uint2* __restrict__ ys)
{
    extern __shared__ uint2 smem2[];
    uint2* sQ = smem2;                 // [32 kw][128 r]
    uint2* sK = sQ + 32 * AQ2;         // [32 kw][64 r]
    uint2* sV = sK + 32 * AK2;         // [32 iw][64 d]

    const int tid  = threadIdx.x;
    const int wid  = tid >> 5;
    const int lane = tid & 31;
    const int g    = lane >> 2;
    const int tig  = lane & 3;
    const int t8   = tig << 3;
    const int wm   = wid * 16;

    const int b  = blockIdx.z;
    const int h  = blockIdx.y;
    const int t0 = blockIdx.x * 128;

    // load Q tile: 128 rows x 32 words
#pragma unroll
    for (int w = 0; w < 16; w++) {
        int idx = tid + 256 * w;
        int r = idx >> 5, dw = idx & 31;
        sQ[qidx(dw, r)] = qs[(size_t)(b * T_DIM + t0 + r) * 512 + h * 32 + dw];
    }

    float yacc[8][4];
#pragma unroll
    for (int dt = 0; dt < 8; dt++)
#pragma unroll
        for (int r = 0; r < 4; r++) yacc[dt][r] = 0.f;
    float m0r = -1e30f, m1r = -1e30f;
    float l0r = 0.f, l1r = 0.f;

    __syncthreads();

    for (int c = 0; c < 9; c++) {
        const int i0 = c * 64;
        // load K chunk: 64 rows x 32 words
#pragma unroll
        for (int w = 0; w < 8; w++) {
            int idx = tid + 256 * w;
            int r = idx >> 5, dw = idx & 31;
            sK[kidx(dw, r)] = kvs[(size_t)(b * I_DIM + i0 + r) * 1024 + h * 32 + dw];
        }
        __syncthreads();

        // S = Q K^T for this chunk (warp rows wm+g, wm+g+8; i cols 8nt+2tig..)
        float sacc[8][4];
#pragma unroll
        for (int nt = 0; nt < 8; nt++)
#pragma unroll
            for (int r = 0; r < 4; r++) sacc[nt][r] = 0.f;

#pragma unroll
        for (int ks = 0; ks < 4; ks++) {
            const int kwa = 8 * ks + tig;
            uint2 af[4];
            af[0] = sQ[kwa * AQ2 + ((wm + g) ^ t8)];
            af[1] = sQ[kwa * AQ2 + ((wm + g + 8) ^ t8)];
            af[2] = sQ[(kwa + 4) * AQ2 + ((wm + g) ^ t8)];
            af[3] = sQ[(kwa + 4) * AQ2 + ((wm + g + 8) ^ t8)];
#pragma unroll
            for (int nt = 0; nt < 8; nt++) {
                const int cc = 8 * nt + g;
                uint2 bf2[2];
                bf2[0] = sK[kwa * AK2 + (cc ^ t8)];
                bf2[1] = sK[(kwa + 4) * AK2 + (cc ^ t8)];
                mma_split(sacc[nt], af, bf2);
            }
        }

        // online softmax update (rows wm+g -> index 0, wm+g+8 -> index 1)
        float cm0 = -1e30f, cm1 = -1e30f;
#pragma unroll
        for (int nt = 0; nt < 8; nt++) {
            sacc[nt][0] *= 0.125f; sacc[nt][1] *= 0.125f;
            sacc[nt][2] *= 0.125f; sacc[nt][3] *= 0.125f;
            cm0 = fmaxf(cm0, fmaxf(sacc[nt][0], sacc[nt][1]));
            cm1 = fmaxf(cm1, fmaxf(sacc[nt][2], sacc[nt][3]));
        }
        cm0 = fmaxf(cm0, __shfl_xor_sync(0xffffffffu, cm0, 1));
        cm0 = fmaxf(cm0, __shfl_xor_sync(0xffffffffu, cm0, 2));
        cm1 = fmaxf(cm1, __shfl_xor_sync(0xffffffffu, cm1, 1));
        cm1 = fmaxf(cm1, __shfl_xor_sync(0xffffffffu, cm1, 2));

        const float mn0 = fmaxf(m0r, cm0);
        const float mn1 = fmaxf(m1r, cm1);
        const float f0 = __expf(m0r - mn0);
        const float f1 = __expf(m1r - mn1);

        float cs0 = 0.f, cs1 = 0.f;
#pragma unroll
        for (int nt = 0; nt < 8; nt++) {
            sacc[nt][0] = __expf(sacc[nt][0] - mn0);
            sacc[nt][1] = __expf(sacc[nt][1] - mn0);
            sacc[nt][2] = __expf(sacc[nt][2] - mn1);
            sacc[nt][3] = __expf(sacc[nt][3] - mn1);
            cs0 += sacc[nt][0] + sacc[nt][1];
            cs1 += sacc[nt][2] + sacc[nt][3];
        }
        cs0 += __shfl_xor_sync(0xffffffffu, cs0, 1);
        cs0 += __shfl_xor_sync(0xffffffffu, cs0, 2);
        cs1 += __shfl_xor_sync(0xffffffffu, cs1, 1);
        cs1 += __shfl_xor_sync(0xffffffffu, cs1, 2);

        l0r = l0r * f0 + cs0;  m0r = mn0;
        l1r = l1r * f1 + cs1;  m1r = mn1;
#pragma unroll
        for (int dt = 0; dt < 8; dt++) {
            yacc[dt][0] *= f0; yacc[dt][1] *= f0;
            yacc[dt][2] *= f1; yacc[dt][3] *= f1;
        }

        // load + repack V chunk: word (iw, d) = (V[2iw][d], V[2iw+1][d])
#pragma unroll
        for (int p = 0; p < 4; p++) {
            int P = tid + 256 * p;
            int iw = P >> 5, dv = P & 31;
            uint2 r0 = kvs[(size_t)(b * I_DIM + i0 + 2 * iw) * 1024 + 512 + h * 32 + dv];
            uint2 r1 = kvs[(size_t)(b * I_DIM + i0 + 2 * iw + 1) * 1024 + 512 + h * 32 + dv];
            sV[kidx(iw, 2 * dv)]     = make_uint2(prmt(r0.x, r1.x, 0x5410),
                                                  prmt(r0.y, r1.y, 0x5410));
            sV[kidx(iw, 2 * dv + 1)] = make_uint2(prmt(r0.x, r1.x, 0x7632),
                                                  prmt(r0.y, r1.y, 0x7632));
        }
        __syncthreads();

        // Y += P V  (P fragments from sacc: C->A identity mapping)
#pragma unroll
        for (int ks = 0; ks < 4; ks++) {
            uint2 a[4];
            a[0] = splitw(sacc[2 * ks][0],     sacc[2 * ks][1]);
            a[1] = splitw(sacc[2 * ks][2],     sacc[2 * ks][3]);
            a[2] = splitw(sacc[2 * ks + 1][0], sacc[2 * ks + 1][1]);
            a[3] = splitw(sacc[2 * ks + 1][2], sacc[2 * ks + 1][3]);
            const int kwa = 8 * ks + tig;
#pragma unroll
            for (int dt = 0; dt < 8; dt++) {
                const int cc = 8 * dt + g;
                uint2 bf2[2];
                bf2[0] = sV[kwa * AK2 + (cc ^ t8)];
                bf2[1] = sV[(kwa + 4) * AK2 + (cc ^ t8)];
                mma_split(yacc[dt], a, bf2);
            }
        }
        __syncthreads();   // sV/sK reads done before next chunk's stores
    }

    // epilogue: normalize and write split y
    const float inv0 = 1.0f / l0r;
    const float inv1 = 1.0f / l1r;
    const size_t r0 = (size_t)(b * T_DIM + t0 + wm + g);
#pragma unroll
    for (int dt = 0; dt < 8; dt++) {
        const int col = 8 * dt + 2 * tig;
        const int cw  = h * 32 + (col >> 1);
        ys[r0 * 512 + cw]       = splitw(yacc[dt][0] * inv0, yacc[dt][1] * inv0);
        ys[(r0 + 8) * 512 + cw] = splitw(yacc[dt][2] * inv1, yacc[dt][3] * inv1);
    }
}

// ---------------------------------------------------------------------------
// Launch
// ---------------------------------------------------------------------------
extern "C" void kernel_launch(void* const* d_in, const int* in_sizes, int n_in,
                              void* d_out, int out_size)
{
    const float* x   = (const float*)d_in[0];
    const float* enc = (const float*)d_in[1];
    const float* Wq  = (const float*)d_in[2];
    const float* bq  = (const float*)d_in[3];
    const float* Wkv = (const float*)d_in[4];
    const float* bkv = (const float*)d_in[5];
    const float* Wo  = (const float*)d_in[6];
    const float* bo  = (const float*)d_in[7];
    float* out = (float*)d_out;

    uint2 *xs, *es, *wqs, *wkvs, *wos, *qsp, *kvsp, *ysp;
    cudaGetSymbolAddress((void**)&xs,   g_xs);
    cudaGetSymbolAddress((void**)&es,   g_es);
    cudaGetSymbolAddress((void**)&wqs,  g_wqs);
    cudaGetSymbolAddress((void**)&wkvs, g_wkvs);
    cudaGetSymbolAddress((void**)&wos,  g_wos);
    cudaGetSymbolAddress((void**)&qsp,  g_qs);
    cudaGetSymbolAddress((void**)&kvsp, g_kvs);
    cudaGetSymbolAddress((void**)&ysp,  g_ys);

    cudaFuncSetAttribute(attn_flash,
                         cudaFuncAttributeMaxDynamicSharedMemorySize, ATTN_BYTES);

    // conversions (fp32 -> split planes)
    {
        int n;
        n = BATCH * T_DIM * C_DIM / 2;
        convert_split<<<(n + 255) / 256, 256>>>((const float2*)x, xs, n);
        n = BATCH * I_DIM * C_DIM / 2;
        convert_split<<<(n + 255) / 256, 256>>>((const float2*)enc, es, n);
        n = C_DIM * C_DIM / 2;
        convert_split<<<(n + 255) / 256, 256>>>((const float2*)Wq, wqs, n);
        n = 2 * C_DIM * C_DIM / 2;
        convert_split<<<(n + 255) / 256, 256>>>((const float2*)Wkv, wkvs, n);
        n = C_DIM * C_DIM / 2;
        convert_split<<<(n + 255) / 256, 256>>>((const float2*)Wo, wos, n);
    }

    // Q = x Wq^T + bq  -> split q
    gemm_split<true><<<dim3(C_DIM / 128, BATCH * T_DIM / 128), 256>>>(
        xs, wqs, bq, nullptr, qsp, BATCH * T_DIM, C_DIM, C_DIM / 2);

    // KV = enc Wkv^T + bkv -> split kv
    gemm_split<true><<<dim3(2 * C_DIM / 128, BATCH * I_DIM / 128), 256>>>(
        es, wkvs, bkv, nullptr, kvsp, BATCH * I_DIM, 2 * C_DIM, C_DIM / 2);

    // flash attention -> split y
    attn_flash<<<dim3(T_DIM / 128, N_HEAD, BATCH), 256, ATTN_BYTES>>>(
        qsp, kvsp, ysp);

    // out = y Wo^T + bo  (fp32)
    gemm_split<false><<<dim3(C_DIM / 128, BATCH * T_DIM / 128), 256>>>(
        ysp, wos, bo, out, nullptr, BATCH * T_DIM, C_DIM, C_DIM / 2);
}